// round 6
// baseline (speedup 1.0000x reference)
#include <cuda_runtime.h>
#include <cuda_fp16.h>
#include <cstdint>

// ---------------------------------------------------------------------------
// FlexAttnBlock: x[2,48,48,768] -> qkv proj -> 12-head NATTEN(r=7) -> out proj
// R5: HMMA split-fp16 GEMMs + MMA band-limited flash attention (f16x2 exp).
// ---------------------------------------------------------------------------

#define NBATCH 2
#define HH 48
#define WW 48
#define HW 2304
#define DMODEL 768
#define DHEAD 64
#define NHEADS 12
#define KSZ 7
#define M_X (NBATCH*HW)      // 4608
#define NQKV (3*DMODEL)      // 2304
#define QSCALE 0.1803368801f // 0.125 * log2(e)

// ------------------------- scratch (no allocs allowed) ---------------------
__device__ __align__(16) __half g_qhi[NBATCH*NHEADS*HW*DHEAD], g_qlo[NBATCH*NHEADS*HW*DHEAD];
__device__ __align__(16) __half g_khi[NBATCH*NHEADS*HW*DHEAD], g_klo[NBATCH*NHEADS*HW*DHEAD];
__device__ __align__(16) __half g_vhi[NBATCH*NHEADS*HW*DHEAD], g_vlo[NBATCH*NHEADS*HW*DHEAD];
__device__ __align__(16) __half g_xhi[M_X*DMODEL],    g_xlo[M_X*DMODEL];
__device__ __align__(16) __half g_wqhi[NQKV*DMODEL],  g_wqlo[NQKV*DMODEL];
__device__ __align__(16) __half g_wohi[DMODEL*DMODEL],g_wolo[DMODEL*DMODEL];
__device__ __align__(16) __half g_ohi[M_X*DMODEL],    g_olo[M_X*DMODEL];

// ------------------------- helpers ----------------------------------------
__device__ __forceinline__ uint32_t smem_u32(const void* p) {
    uint32_t a;
    asm("{ .reg .u64 t; cvta.to.shared.u64 t, %1; cvt.u32.u64 %0, t; }" : "=r"(a) : "l"(p));
    return a;
}
__device__ __forceinline__ void ldsm_x4(uint32_t* r, uint32_t addr) {
    asm volatile("ldmatrix.sync.aligned.m8n8.x4.shared.b16 {%0,%1,%2,%3}, [%4];"
                 : "=r"(r[0]), "=r"(r[1]), "=r"(r[2]), "=r"(r[3]) : "r"(addr));
}
__device__ __forceinline__ void ldsm_x4t(uint32_t* r, uint32_t addr) {
    asm volatile("ldmatrix.sync.aligned.m8n8.x4.trans.shared.b16 {%0,%1,%2,%3}, [%4];"
                 : "=r"(r[0]), "=r"(r[1]), "=r"(r[2]), "=r"(r[3]) : "r"(addr));
}
__device__ __forceinline__ void ldsm_x2(uint32_t* r, uint32_t addr) {
    asm volatile("ldmatrix.sync.aligned.m8n8.x2.shared.b16 {%0,%1}, [%2];"
                 : "=r"(r[0]), "=r"(r[1]) : "r"(addr));
}
__device__ __forceinline__ void mma16816(float* c, const uint32_t* a, const uint32_t* b) {
    asm volatile(
        "mma.sync.aligned.m16n8k16.row.col.f32.f16.f16.f32 "
        "{%0,%1,%2,%3},{%4,%5,%6,%7},{%8,%9},{%0,%1,%2,%3};"
        : "+f"(c[0]), "+f"(c[1]), "+f"(c[2]), "+f"(c[3])
        : "r"(a[0]), "r"(a[1]), "r"(a[2]), "r"(a[3]), "r"(b[0]), "r"(b[1]));
}
__device__ __forceinline__ void cp16(uint32_t saddr, const void* gaddr) {
    asm volatile("cp.async.cg.shared.global [%0], [%1], 16;" :: "r"(saddr), "l"(gaddr));
}
__device__ __forceinline__ void cp_commit() { asm volatile("cp.async.commit_group;"); }
template<int N> __device__ __forceinline__ void cp_wait() {
    asm volatile("cp.async.wait_group %0;" :: "n"(N));
}
__device__ __forceinline__ float ex2f(float x) {
    float y; asm("ex2.approx.ftz.f32 %0, %1;" : "=f"(y) : "f"(x)); return y;
}
__device__ __forceinline__ uint32_t f16x2pack(float hi, float lo) {
    uint32_t r; asm("cvt.rn.f16x2.f32 %0, %1, %2;" : "=r"(r) : "f"(hi), "f"(lo)); return r;
}
__device__ __forceinline__ uint32_t ex2h2(uint32_t x) {
    uint32_t r; asm("ex2.approx.f16x2 %0, %1;" : "=r"(r) : "r"(x)); return r;
}
// 128B-row swizzle (rows of 64 fp16)
__device__ __forceinline__ uint32_t swz128(int r, int c16) {
    return (uint32_t)(r * 128 + ((c16 ^ (r & 7)) << 4));
}

// ------------------------- fp32 -> fp16 hi/lo split ------------------------
template<int DST>
__global__ void split_kernel(const float4* __restrict__ src, int n4)
{
    __half* hi = (DST == 0) ? g_xhi : (DST == 1) ? g_wqhi : g_wohi;
    __half* lo = (DST == 0) ? g_xlo : (DST == 1) ? g_wqlo : g_wolo;
    int i = blockIdx.x * 256 + threadIdx.x;
    if (i >= n4) return;
    float4 v = src[i];
    __half h0 = __float2half(v.x), h1 = __float2half(v.y);
    __half h2 = __float2half(v.z), h3 = __float2half(v.w);
    __half2 hp0; hp0.x = h0; hp0.y = h1;
    __half2 hp1; hp1.x = h2; hp1.y = h3;
    __half2 lp0; lp0.x = __float2half(v.x - __half2float(h0));
                 lp0.y = __float2half(v.y - __half2float(h1));
    __half2 lp1; lp1.x = __float2half(v.z - __half2float(h2));
                 lp1.y = __float2half(v.w - __half2float(h3));
    *(__half2*)&hi[4*i]     = hp0;
    *(__half2*)&hi[4*i + 2] = hp1;
    *(__half2*)&lo[4*i]     = lp0;
    *(__half2*)&lo[4*i + 2] = lp1;
}

// ------------------------- HMMA GEMM (proven R3 mainloop) ------------------
#define NSTAGE 3
#define STAGE_BYTES 32768
#define SMEM_GEMM (NSTAGE * STAGE_BYTES)
#define KSTEPS 24

__device__ __forceinline__ uint32_t swz(int r, int c) {   // 64B-row swizzle
    return (uint32_t)(r * 64 + ((c ^ (r & 3)) << 4));
}

__device__ __forceinline__ void issue_stage(
    uint32_t sbase, int bm, int bn, int k0,
    const __half* __restrict__ Ahi, const __half* __restrict__ Alo,
    const __half* __restrict__ Bhi, const __half* __restrict__ Blo)
{
    const int tid = threadIdx.x;
    #pragma unroll
    for (int i = 0; i < 8; ++i) {
        const int id  = tid + i * 256;
        const int arr = id >> 9;
        const int u   = id & 511;
        const int r   = u >> 2;
        const int c   = u & 3;
        const __half* src = (arr == 0) ? Ahi : (arr == 1) ? Alo : (arr == 2) ? Bhi : Blo;
        const int grow = ((arr < 2) ? bm : bn) + r;
        cp16(sbase + arr * 8192 + swz(r, c), src + (size_t)grow * DMODEL + k0 + c * 8);
    }
}

template<int EPI>
__global__ __launch_bounds__(256, 1)
void gemm_mma(float* __restrict__ C)
{
    extern __shared__ __align__(128) char smem[];
    const uint32_t sb0 = smem_u32(smem);
    const int tid  = threadIdx.x;
    const int wid  = tid >> 5;
    const int lane = tid & 31;
    const int wm   = wid & 1;
    const int wn   = wid >> 1;
    const int bm   = blockIdx.y * 128;
    const int bn   = blockIdx.x * 128;

    const __half* __restrict__ Ahi = (EPI == 0) ? g_xhi : g_ohi;
    const __half* __restrict__ Alo = (EPI == 0) ? g_xlo : g_olo;
    const __half* __restrict__ Bhi = (EPI == 0) ? g_wqhi : g_wohi;
    const __half* __restrict__ Blo = (EPI == 0) ? g_wqlo : g_wolo;

    float acc[4][4][4];
    #pragma unroll
    for (int a = 0; a < 4; ++a)
        #pragma unroll
        for (int b = 0; b < 4; ++b)
            #pragma unroll
            for (int d = 0; d < 4; ++d) acc[a][b][d] = 0.f;

    issue_stage(sb0,               bm, bn, 0,  Ahi, Alo, Bhi, Blo); cp_commit();
    issue_stage(sb0 + STAGE_BYTES, bm, bn, 32, Ahi, Alo, Bhi, Blo); cp_commit();

    const int a_row = (lane & 7) + ((lane >> 3) & 1) * 8;
    const int a_chk = (lane >> 4);
    const int t16   = lane & 15;
    const int b_row = (t16 & 7);
    const int b_chk = (t16 >> 3);

    for (int s = 0; s < KSTEPS; ++s) {
        if (s == KSTEPS - 1) cp_wait<0>(); else cp_wait<1>();
        __syncthreads();
        if (s + 2 < KSTEPS) {
            issue_stage(sb0 + ((s + 2) % NSTAGE) * STAGE_BYTES, bm, bn, (s + 2) * 32,
                        Ahi, Alo, Bhi, Blo);
            cp_commit();
        }
        const uint32_t sb  = sb0 + (s % NSTAGE) * STAGE_BYTES;
        const uint32_t sAh = sb, sAl = sb + 8192, sBh = sb + 16384, sBl = sb + 24576;

        #pragma unroll
        for (int h = 0; h < 2; ++h) {
            uint32_t ah[4][4], al[4][4], bh[4][2], bl[4][2];
            #pragma unroll
            for (int mt = 0; mt < 4; ++mt) {
                const int row = wm * 64 + mt * 16 + a_row;
                const uint32_t off = swz(row, 2 * h + a_chk);
                ldsm_x4(ah[mt], sAh + off);
                ldsm_x4(al[mt], sAl + off);
            }
            #pragma unroll
            for (int nt = 0; nt < 4; ++nt) {
                const int row = wn * 32 + nt * 8 + b_row;
                const uint32_t off = swz(row, 2 * h + b_chk);
                ldsm_x2(bh[nt], sBh + off);
                ldsm_x2(bl[nt], sBl + off);
            }
            #pragma unroll
            for (int mt = 0; mt < 4; ++mt)
                #pragma unroll
                for (int nt = 0; nt < 4; ++nt) {
                    mma16816(acc[mt][nt], ah[mt], bh[nt]);
                    mma16816(acc[mt][nt], ah[mt], bl[nt]);
                    mma16816(acc[mt][nt], al[mt], bh[nt]);
                }
        }
    }

    const int g  = lane >> 2;
    const int ti = lane & 3;
    #pragma unroll
    for (int mt = 0; mt < 4; ++mt) {
        #pragma unroll
        for (int nt = 0; nt < 4; ++nt) {
            const int gm0 = bm + wm * 64 + mt * 16 + g;
            const int gn  = bn + wn * 32 + nt * 8 + ti * 2;
            if (EPI == 0) {
                const int sel  = gn / DMODEL;
                const int rem  = gn - sel * DMODEL;
                const int head = rem >> 6;
                const int e    = rem & 63;
                __half* dh = (sel == 0) ? g_qhi : (sel == 1) ? g_khi : g_vhi;
                __half* dl = (sel == 0) ? g_qlo : (sel == 1) ? g_klo : g_vlo;
                const float osc = (sel == 0) ? QSCALE : 1.f;
                #pragma unroll
                for (int rr = 0; rr < 2; ++rr) {
                    const int gm  = gm0 + rr * 8;
                    const int n   = gm / HW;
                    const int idx = gm - n * HW;
                    float v0 = acc[mt][nt][rr * 2] * osc;
                    float v1 = acc[mt][nt][rr * 2 + 1] * osc;
                    __half h0 = __float2half(v0), h1 = __float2half(v1);
                    __half2 hp; hp.x = h0; hp.y = h1;
                    __half2 lp; lp.x = __float2half(v0 - __half2float(h0));
                                lp.y = __float2half(v1 - __half2float(h1));
                    const size_t base = (((size_t)n * NHEADS + head) * HW + idx) * DHEAD + e;
                    *(__half2*)&dh[base] = hp;
                    *(__half2*)&dl[base] = lp;
                }
            } else {
                #pragma unroll
                for (int rr = 0; rr < 2; ++rr) {
                    float2 v2; v2.x = acc[mt][nt][rr * 2]; v2.y = acc[mt][nt][rr * 2 + 1];
                    *(float2*)&C[(size_t)(gm0 + rr * 8) * DMODEL + gn] = v2;
                }
            }
        }
    }
}

// ---------------------------------------------------------------------------
// MMA NATTEN flash attention. CTA = (slice, qx): 48 queries, 4 warps.
// Warps 0..2 compute m16 query tiles; per kx stage K/V hi/lo (double buffer).
// ---------------------------------------------------------------------------
#define SM_ATTN 61440   // 12KB Q + 2 stages x 24KB

__device__ __forceinline__ void attn_load_stage(uint32_t smb, size_t gb, int s)
{
    const uint32_t sb = smb + 12288 + s * 24576;
    const int tid = threadIdx.x;
    #pragma unroll
    for (int i = 0; i < 12; ++i) {
        const int id  = tid + i * 128;       // 0..1535
        const int arr = id / 384;            // 0..3
        const int u   = id - arr * 384;
        const int r   = u >> 3;              // 0..47
        const int c   = u & 7;
        const __half* src = (arr == 0) ? g_khi : (arr == 1) ? g_klo :
                            (arr == 2) ? g_vhi : g_vlo;
        cp16(sb + arr * 6144 + swz128(r, c), src + gb + (size_t)r * DHEAD + c * 8);
    }
}

__global__ __launch_bounds__(128, 2)
void natten_mma_kernel()
{
    extern __shared__ __align__(128) char sm[];
    const uint32_t smb = smem_u32(sm);
    const int tid = threadIdx.x, w = tid >> 5, lane = tid & 31;
    const int blk = blockIdx.x;
    const int slice = blk / HH;
    const int qx = blk - slice * HH;
    const size_t sbase = (size_t)slice * HW * DHEAD;

    const uint32_t SQH = smb, SQL = smb + 6144;

    // prologue: stage Q row [48,64] hi/lo
    {
        const __half* gqh = g_qhi + sbase + (size_t)qx * WW * DHEAD;
        const __half* gql = g_qlo + sbase + (size_t)qx * WW * DHEAD;
        #pragma unroll
        for (int i = 0; i < 6; ++i) {
            const int id  = tid + i * 128;   // 0..767
            const int arr = (id >= 384);
            const int u   = id - arr * 384;
            const int r   = u >> 3;
            const int c   = u & 7;
            const __half* src = arr ? gql : gqh;
            cp16((arr ? SQL : SQH) + swz128(r, c), src + (size_t)r * DHEAD + c * 8);
        }
    }
    const int kx0 = max(qx - KSZ, 0), kx1 = min(qx + KSZ, HH - 1);
    const int nkx = kx1 - kx0 + 1;
    attn_load_stage(smb, sbase + (size_t)kx0 * WW * DHEAD, 0);
    cp_commit();

    const int g = lane >> 2, ti = lane & 3;
    const int Bn = (w == 0) ? 0 : (w == 1) ? 8 : 24;   // first ky of band tiles
    const int NT = (w == 1) ? 4 : 3;                   // n8 tiles in band
    const int qyA = 16 * w + g, qyB = qyA + 8;
    uint32_t vm = 0;
    #pragma unroll
    for (int t = 0; t < 4; ++t) {
        const int ky = Bn + 8 * t + 2 * ti;
        if (abs(ky     - qyA) <= KSZ) vm |= 1u << (t * 4 + 0);
        if (abs(ky + 1 - qyA) <= KSZ) vm |= 1u << (t * 4 + 1);
        if (abs(ky     - qyB) <= KSZ) vm |= 1u << (t * 4 + 2);
        if (abs(ky + 1 - qyB) <= KSZ) vm |= 1u << (t * 4 + 3);
    }

    float m0 = -1e30f, m1 = -1e30f, l0 = 0.f, l1 = 0.f;
    float o[8][4];
    #pragma unroll
    for (int n = 0; n < 8; ++n)
        #pragma unroll
        for (int j = 0; j < 4; ++j) o[n][j] = 0.f;
    uint32_t qh[4][4], ql[4][4];

    const int a_row  = (lane & 7) + ((lane >> 3) & 1) * 8;
    const int a_chk  = lane >> 4;
    const int kb_row = lane & 7, kb_k = (lane >> 3) & 1, kb_t = lane >> 4;
    const int v_row  = (lane & 7) + ((lane >> 3) & 1) * 8;
    const int v_chk  = lane >> 4;

    for (int i = 0; i < nkx; ++i) {
        __syncthreads();     // prior-iter readers done before overwriting buffer
        if (i + 1 < nkx) {
            attn_load_stage(smb, sbase + (size_t)(kx0 + i + 1) * WW * DHEAD, (i + 1) & 1);
            cp_commit();
            cp_wait<1>();
        } else cp_wait<0>();
        __syncthreads();

        if (i == 0 && w < 3) {
            #pragma unroll
            for (int kc = 0; kc < 4; ++kc) {
                const uint32_t off = swz128(16 * w + a_row, 2 * kc + a_chk);
                ldsm_x4(qh[kc], SQH + off);
                ldsm_x4(ql[kc], SQL + off);
            }
        }
        if (w >= 3) continue;

        const uint32_t sb = smb + 12288 + (i & 1) * 24576;
        const uint32_t KH = sb, KL = sb + 6144, VH = sb + 12288, VL = sb + 18432;

        // ---- S = Q K^T (split fp16) on band tiles
        float sc4[4][4];
        #pragma unroll
        for (int t = 0; t < 4; ++t)
            #pragma unroll
            for (int j = 0; j < 4; ++j) sc4[t][j] = 0.f;
        #pragma unroll
        for (int kc = 0; kc < 4; ++kc) {
            #pragma unroll
            for (int pr = 0; pr < 2; ++pr) {
                uint32_t bh[4], bl[4];
                const uint32_t off = swz128(Bn + 8 * (2 * pr + kb_t) + kb_row, 2 * kc + kb_k);
                ldsm_x4(bh, KH + off);
                ldsm_x4(bl, KL + off);
                mma16816(sc4[2 * pr], qh[kc], bh + 0);
                mma16816(sc4[2 * pr], qh[kc], bl + 0);
                mma16816(sc4[2 * pr], ql[kc], bh + 0);
                if (2 * pr + 1 < NT) {
                    mma16816(sc4[2 * pr + 1], qh[kc], bh + 2);
                    mma16816(sc4[2 * pr + 1], qh[kc], bl + 2);
                    mma16816(sc4[2 * pr + 1], ql[kc], bh + 2);
                }
            }
        }
        // ---- mask invalid (|qy-ky| > 7)
        #pragma unroll
        for (int t = 0; t < 4; ++t)
            #pragma unroll
            for (int j = 0; j < 4; ++j)
                if (!((vm >> (t * 4 + j)) & 1)) sc4[t][j] = -1e30f;
        // ---- online softmax (exp2 domain; q pre-scaled)
        float rm0 = -1e30f, rm1 = -1e30f;
        #pragma unroll
        for (int t = 0; t < 4; ++t) {
            if (t < NT) {
                rm0 = fmaxf(rm0, fmaxf(sc4[t][0], sc4[t][1]));
                rm1 = fmaxf(rm1, fmaxf(sc4[t][2], sc4[t][3]));
            }
        }
        rm0 = fmaxf(rm0, __shfl_xor_sync(0xffffffffu, rm0, 1));
        rm0 = fmaxf(rm0, __shfl_xor_sync(0xffffffffu, rm0, 2));
        rm1 = fmaxf(rm1, __shfl_xor_sync(0xffffffffu, rm1, 1));
        rm1 = fmaxf(rm1, __shfl_xor_sync(0xffffffffu, rm1, 2));
        if (rm0 > m0) {
            const float c0 = ex2f(m0 - rm0);
            l0 *= c0;
            #pragma unroll
            for (int n = 0; n < 8; ++n) { o[n][0] *= c0; o[n][1] *= c0; }
            m0 = rm0;
        }
        if (rm1 > m1) {
            const float c1 = ex2f(m1 - rm1);
            l1 *= c1;
            #pragma unroll
            for (int n = 0; n < 8; ++n) { o[n][2] *= c1; o[n][3] *= c1; }
            m1 = rm1;
        }
        uint32_t P01[4], P23[4];
        P01[3] = P23[3] = 0u;
        #pragma unroll
        for (int t = 0; t < 4; ++t) {
            if (t < NT) {
                P01[t] = ex2h2(f16x2pack(sc4[t][1] - m0, sc4[t][0] - m0));
                P23[t] = ex2h2(f16x2pack(sc4[t][3] - m1, sc4[t][2] - m1));
                const float2 fa = __half22float2(*(__half2*)&P01[t]);
                const float2 fb = __half22float2(*(__half2*)&P23[t]);
                l0 += fa.x + fa.y;
                l1 += fb.x + fb.y;
            }
        }
        // ---- O += P V (Vhi + Vlo)
        auto pv = [&](int c, uint32_t a0, uint32_t a1, uint32_t a2, uint32_t a3) {
            const uint32_t A[4] = {a0, a1, a2, a3};
            #pragma unroll
            for (int np = 0; np < 4; ++np) {
                uint32_t vh[4], vl[4];
                const uint32_t off = swz128(16 * c + v_row, 2 * np + v_chk);
                ldsm_x4t(vh, VH + off);
                ldsm_x4t(vl, VL + off);
                mma16816(o[2 * np],     A, vh + 0);
                mma16816(o[2 * np + 1], A, vh + 2);
                mma16816(o[2 * np],     A, vl + 0);
                mma16816(o[2 * np + 1], A, vl + 2);
            }
        };
        if (w == 0) {
            pv(0, P01[0], P23[0], P01[1], P23[1]);
            pv(1, P01[2], P23[2], 0u, 0u);
        } else if (w == 1) {
            pv(0, 0u, 0u, P01[0], P23[0]);
            pv(1, P01[1], P23[1], P01[2], P23[2]);
            pv(2, P01[3], P23[3], 0u, 0u);
        } else {
            pv(1, 0u, 0u, P01[0], P23[0]);
            pv(2, P01[1], P23[1], P01[2], P23[2]);
        }
    }

    // ---- finalize: l reduce over quad, normalize, write fp16 hi/lo o
    if (w < 3) {
        l0 += __shfl_xor_sync(0xffffffffu, l0, 1);
        l0 += __shfl_xor_sync(0xffffffffu, l0, 2);
        l1 += __shfl_xor_sync(0xffffffffu, l1, 1);
        l1 += __shfl_xor_sync(0xffffffffu, l1, 2);
        const float inv0 = 1.f / l0, inv1 = 1.f / l1;
        const int nb = slice / NHEADS, head = slice - nb * NHEADS;
        const size_t rowA = ((size_t)nb * HW + (size_t)qx * WW + qyA) * DMODEL + head * DHEAD;
        const size_t rowB = ((size_t)nb * HW + (size_t)qx * WW + qyB) * DMODEL + head * DHEAD;
        #pragma unroll
        for (int np = 0; np < 8; ++np) {
            const int d = np * 8 + 2 * ti;
            {
                const float v0 = o[np][0] * inv0, v1 = o[np][1] * inv0;
                __half h0 = __float2half(v0), h1 = __float2half(v1);
                __half2 hp; hp.x = h0; hp.y = h1;
                __half2 lp; lp.x = __float2half(v0 - __half2float(h0));
                            lp.y = __float2half(v1 - __half2float(h1));
                *(__half2*)&g_ohi[rowA + d] = hp;
                *(__half2*)&g_olo[rowA + d] = lp;
            }
            {
                const float v0 = o[np][2] * inv1, v1 = o[np][3] * inv1;
                __half h0 = __float2half(v0), h1 = __float2half(v1);
                __half2 hp; hp.x = h0; hp.y = h1;
                __half2 lp; lp.x = __float2half(v0 - __half2float(h0));
                            lp.y = __float2half(v1 - __half2float(h1));
                *(__half2*)&g_ohi[rowB + d] = hp;
                *(__half2*)&g_olo[rowB + d] = lp;
            }
        }
    }
}

// ---------------------------------------------------------------------------
extern "C" void kernel_launch(void* const* d_in, const int* in_sizes, int n_in,
                              void* d_out, int out_size)
{
    const float* x     = (const float*)d_in[0];
    const float* w_qkv = (const float*)d_in[1];
    const float* w_out = (const float*)d_in[2];
    float* out = (float*)d_out;

    (void)cudaFuncSetAttribute(gemm_mma<0>, cudaFuncAttributeMaxDynamicSharedMemorySize, SMEM_GEMM);
    (void)cudaFuncSetAttribute(gemm_mma<1>, cudaFuncAttributeMaxDynamicSharedMemorySize, SMEM_GEMM);
    (void)cudaFuncSetAttribute(natten_mma_kernel, cudaFuncAttributeMaxDynamicSharedMemorySize, SM_ATTN);

    // 0) fp32 -> fp16 hi/lo splits
    {
        int n4 = M_X * DMODEL / 4;
        split_kernel<0><<<(n4 + 255) / 256, 256>>>((const float4*)x, n4);
        n4 = NQKV * DMODEL / 4;
        split_kernel<1><<<(n4 + 255) / 256, 256>>>((const float4*)w_qkv, n4);
        n4 = DMODEL * DMODEL / 4;
        split_kernel<2><<<(n4 + 255) / 256, 256>>>((const float4*)w_out, n4);
    }

    // 1) QKV projection: emits q(scaled)/k/v fp16 hi/lo
    gemm_mma<0><<<dim3(NQKV / 128, M_X / 128), 256, SMEM_GEMM>>>(nullptr);

    // 2) Neighborhood attention: 24 slices x 48 qx rows
    natten_mma_kernel<<<NBATCH * NHEADS * HH, 128, SM_ATTN>>>();

    // 3) Output projection: [4608,768] x [768,768]^T
    gemm_mma<1><<<dim3(DMODEL / 128, M_X / 128), 256, SMEM_GEMM>>>(out);
}

// round 7
// speedup vs baseline: 1.0003x; 1.0003x over previous
#include <cuda_runtime.h>
#include <cuda_fp16.h>
#include <cstdint>

// ---------------------------------------------------------------------------
// FlexAttnBlock: x[2,48,48,768] -> qkv proj -> 12-head NATTEN(r=7) -> out proj
// R5: HMMA split-fp16 GEMMs + MMA band-limited flash attention (f16x2 exp).
// ---------------------------------------------------------------------------

#define NBATCH 2
#define HH 48
#define WW 48
#define HW 2304
#define DMODEL 768
#define DHEAD 64
#define NHEADS 12
#define KSZ 7
#define M_X (NBATCH*HW)      // 4608
#define NQKV (3*DMODEL)      // 2304
#define QSCALE 0.1803368801f // 0.125 * log2(e)

// ------------------------- scratch (no allocs allowed) ---------------------
__device__ __align__(16) __half g_qhi[NBATCH*NHEADS*HW*DHEAD], g_qlo[NBATCH*NHEADS*HW*DHEAD];
__device__ __align__(16) __half g_khi[NBATCH*NHEADS*HW*DHEAD], g_klo[NBATCH*NHEADS*HW*DHEAD];
__device__ __align__(16) __half g_vhi[NBATCH*NHEADS*HW*DHEAD], g_vlo[NBATCH*NHEADS*HW*DHEAD];
__device__ __align__(16) __half g_xhi[M_X*DMODEL],    g_xlo[M_X*DMODEL];
__device__ __align__(16) __half g_wqhi[NQKV*DMODEL],  g_wqlo[NQKV*DMODEL];
__device__ __align__(16) __half g_wohi[DMODEL*DMODEL],g_wolo[DMODEL*DMODEL];
__device__ __align__(16) __half g_ohi[M_X*DMODEL],    g_olo[M_X*DMODEL];

// ------------------------- helpers ----------------------------------------
__device__ __forceinline__ uint32_t smem_u32(const void* p) {
    uint32_t a;
    asm("{ .reg .u64 t; cvta.to.shared.u64 t, %1; cvt.u32.u64 %0, t; }" : "=r"(a) : "l"(p));
    return a;
}
__device__ __forceinline__ void ldsm_x4(uint32_t* r, uint32_t addr) {
    asm volatile("ldmatrix.sync.aligned.m8n8.x4.shared.b16 {%0,%1,%2,%3}, [%4];"
                 : "=r"(r[0]), "=r"(r[1]), "=r"(r[2]), "=r"(r[3]) : "r"(addr));
}
__device__ __forceinline__ void ldsm_x4t(uint32_t* r, uint32_t addr) {
    asm volatile("ldmatrix.sync.aligned.m8n8.x4.trans.shared.b16 {%0,%1,%2,%3}, [%4];"
                 : "=r"(r[0]), "=r"(r[1]), "=r"(r[2]), "=r"(r[3]) : "r"(addr));
}
__device__ __forceinline__ void ldsm_x2(uint32_t* r, uint32_t addr) {
    asm volatile("ldmatrix.sync.aligned.m8n8.x2.shared.b16 {%0,%1}, [%2];"
                 : "=r"(r[0]), "=r"(r[1]) : "r"(addr));
}
__device__ __forceinline__ void mma16816(float* c, const uint32_t* a, const uint32_t* b) {
    asm volatile(
        "mma.sync.aligned.m16n8k16.row.col.f32.f16.f16.f32 "
        "{%0,%1,%2,%3},{%4,%5,%6,%7},{%8,%9},{%0,%1,%2,%3};"
        : "+f"(c[0]), "+f"(c[1]), "+f"(c[2]), "+f"(c[3])
        : "r"(a[0]), "r"(a[1]), "r"(a[2]), "r"(a[3]), "r"(b[0]), "r"(b[1]));
}
__device__ __forceinline__ void cp16(uint32_t saddr, const void* gaddr) {
    asm volatile("cp.async.cg.shared.global [%0], [%1], 16;" :: "r"(saddr), "l"(gaddr));
}
__device__ __forceinline__ void cp_commit() { asm volatile("cp.async.commit_group;"); }
template<int N> __device__ __forceinline__ void cp_wait() {
    asm volatile("cp.async.wait_group %0;" :: "n"(N));
}
__device__ __forceinline__ float ex2f(float x) {
    float y; asm("ex2.approx.ftz.f32 %0, %1;" : "=f"(y) : "f"(x)); return y;
}
__device__ __forceinline__ uint32_t f16x2pack(float hi, float lo) {
    uint32_t r; asm("cvt.rn.f16x2.f32 %0, %1, %2;" : "=r"(r) : "f"(hi), "f"(lo)); return r;
}
__device__ __forceinline__ uint32_t ex2h2(uint32_t x) {
    uint32_t r; asm("ex2.approx.f16x2 %0, %1;" : "=r"(r) : "r"(x)); return r;
}
// 128B-row swizzle (rows of 64 fp16)
__device__ __forceinline__ uint32_t swz128(int r, int c16) {
    return (uint32_t)(r * 128 + ((c16 ^ (r & 7)) << 4));
}

// ------------------------- fp32 -> fp16 hi/lo split ------------------------
template<int DST>
__global__ void split_kernel(const float4* __restrict__ src, int n4)
{
    __half* hi = (DST == 0) ? g_xhi : (DST == 1) ? g_wqhi : g_wohi;
    __half* lo = (DST == 0) ? g_xlo : (DST == 1) ? g_wqlo : g_wolo;
    int i = blockIdx.x * 256 + threadIdx.x;
    if (i >= n4) return;
    float4 v = src[i];
    __half h0 = __float2half(v.x), h1 = __float2half(v.y);
    __half h2 = __float2half(v.z), h3 = __float2half(v.w);
    __half2 hp0; hp0.x = h0; hp0.y = h1;
    __half2 hp1; hp1.x = h2; hp1.y = h3;
    __half2 lp0; lp0.x = __float2half(v.x - __half2float(h0));
                 lp0.y = __float2half(v.y - __half2float(h1));
    __half2 lp1; lp1.x = __float2half(v.z - __half2float(h2));
                 lp1.y = __float2half(v.w - __half2float(h3));
    *(__half2*)&hi[4*i]     = hp0;
    *(__half2*)&hi[4*i + 2] = hp1;
    *(__half2*)&lo[4*i]     = lp0;
    *(__half2*)&lo[4*i + 2] = lp1;
}

// ------------------------- HMMA GEMM (proven R3 mainloop) ------------------
#define NSTAGE 3
#define STAGE_BYTES 32768
#define SMEM_GEMM (NSTAGE * STAGE_BYTES)
#define KSTEPS 24

__device__ __forceinline__ uint32_t swz(int r, int c) {   // 64B-row swizzle
    return (uint32_t)(r * 64 + ((c ^ (r & 3)) << 4));
}

__device__ __forceinline__ void issue_stage(
    uint32_t sbase, int bm, int bn, int k0,
    const __half* __restrict__ Ahi, const __half* __restrict__ Alo,
    const __half* __restrict__ Bhi, const __half* __restrict__ Blo)
{
    const int tid = threadIdx.x;
    #pragma unroll
    for (int i = 0; i < 8; ++i) {
        const int id  = tid + i * 256;
        const int arr = id >> 9;
        const int u   = id & 511;
        const int r   = u >> 2;
        const int c   = u & 3;
        const __half* src = (arr == 0) ? Ahi : (arr == 1) ? Alo : (arr == 2) ? Bhi : Blo;
        const int grow = ((arr < 2) ? bm : bn) + r;
        cp16(sbase + arr * 8192 + swz(r, c), src + (size_t)grow * DMODEL + k0 + c * 8);
    }
}

template<int EPI>
__global__ __launch_bounds__(256, 1)
void gemm_mma(float* __restrict__ C)
{
    extern __shared__ __align__(128) char smem[];
    const uint32_t sb0 = smem_u32(smem);
    const int tid  = threadIdx.x;
    const int wid  = tid >> 5;
    const int lane = tid & 31;
    const int wm   = wid & 1;
    const int wn   = wid >> 1;
    const int bm   = blockIdx.y * 128;
    const int bn   = blockIdx.x * 128;

    const __half* __restrict__ Ahi = (EPI == 0) ? g_xhi : g_ohi;
    const __half* __restrict__ Alo = (EPI == 0) ? g_xlo : g_olo;
    const __half* __restrict__ Bhi = (EPI == 0) ? g_wqhi : g_wohi;
    const __half* __restrict__ Blo = (EPI == 0) ? g_wqlo : g_wolo;

    float acc[4][4][4];
    #pragma unroll
    for (int a = 0; a < 4; ++a)
        #pragma unroll
        for (int b = 0; b < 4; ++b)
            #pragma unroll
            for (int d = 0; d < 4; ++d) acc[a][b][d] = 0.f;

    issue_stage(sb0,               bm, bn, 0,  Ahi, Alo, Bhi, Blo); cp_commit();
    issue_stage(sb0 + STAGE_BYTES, bm, bn, 32, Ahi, Alo, Bhi, Blo); cp_commit();

    const int a_row = (lane & 7) + ((lane >> 3) & 1) * 8;
    const int a_chk = (lane >> 4);
    const int t16   = lane & 15;
    const int b_row = (t16 & 7);
    const int b_chk = (t16 >> 3);

    for (int s = 0; s < KSTEPS; ++s) {
        if (s == KSTEPS - 1) cp_wait<0>(); else cp_wait<1>();
        __syncthreads();
        if (s + 2 < KSTEPS) {
            issue_stage(sb0 + ((s + 2) % NSTAGE) * STAGE_BYTES, bm, bn, (s + 2) * 32,
                        Ahi, Alo, Bhi, Blo);
            cp_commit();
        }
        const uint32_t sb  = sb0 + (s % NSTAGE) * STAGE_BYTES;
        const uint32_t sAh = sb, sAl = sb + 8192, sBh = sb + 16384, sBl = sb + 24576;

        #pragma unroll
        for (int h = 0; h < 2; ++h) {
            uint32_t ah[4][4], al[4][4], bh[4][2], bl[4][2];
            #pragma unroll
            for (int mt = 0; mt < 4; ++mt) {
                const int row = wm * 64 + mt * 16 + a_row;
                const uint32_t off = swz(row, 2 * h + a_chk);
                ldsm_x4(ah[mt], sAh + off);
                ldsm_x4(al[mt], sAl + off);
            }
            #pragma unroll
            for (int nt = 0; nt < 4; ++nt) {
                const int row = wn * 32 + nt * 8 + b_row;
                const uint32_t off = swz(row, 2 * h + b_chk);
                ldsm_x2(bh[nt], sBh + off);
                ldsm_x2(bl[nt], sBl + off);
            }
            #pragma unroll
            for (int mt = 0; mt < 4; ++mt)
                #pragma unroll
                for (int nt = 0; nt < 4; ++nt) {
                    mma16816(acc[mt][nt], ah[mt], bh[nt]);
                    mma16816(acc[mt][nt], ah[mt], bl[nt]);
                    mma16816(acc[mt][nt], al[mt], bh[nt]);
                }
        }
    }

    const int g  = lane >> 2;
    const int ti = lane & 3;
    #pragma unroll
    for (int mt = 0; mt < 4; ++mt) {
        #pragma unroll
        for (int nt = 0; nt < 4; ++nt) {
            const int gm0 = bm + wm * 64 + mt * 16 + g;
            const int gn  = bn + wn * 32 + nt * 8 + ti * 2;
            if (EPI == 0) {
                const int sel  = gn / DMODEL;
                const int rem  = gn - sel * DMODEL;
                const int head = rem >> 6;
                const int e    = rem & 63;
                __half* dh = (sel == 0) ? g_qhi : (sel == 1) ? g_khi : g_vhi;
                __half* dl = (sel == 0) ? g_qlo : (sel == 1) ? g_klo : g_vlo;
                const float osc = (sel == 0) ? QSCALE : 1.f;
                #pragma unroll
                for (int rr = 0; rr < 2; ++rr) {
                    const int gm  = gm0 + rr * 8;
                    const int n   = gm / HW;
                    const int idx = gm - n * HW;
                    float v0 = acc[mt][nt][rr * 2] * osc;
                    float v1 = acc[mt][nt][rr * 2 + 1] * osc;
                    __half h0 = __float2half(v0), h1 = __float2half(v1);
                    __half2 hp; hp.x = h0; hp.y = h1;
                    __half2 lp; lp.x = __float2half(v0 - __half2float(h0));
                                lp.y = __float2half(v1 - __half2float(h1));
                    const size_t base = (((size_t)n * NHEADS + head) * HW + idx) * DHEAD + e;
                    *(__half2*)&dh[base] = hp;
                    *(__half2*)&dl[base] = lp;
                }
            } else {
                #pragma unroll
                for (int rr = 0; rr < 2; ++rr) {
                    float2 v2; v2.x = acc[mt][nt][rr * 2]; v2.y = acc[mt][nt][rr * 2 + 1];
                    *(float2*)&C[(size_t)(gm0 + rr * 8) * DMODEL + gn] = v2;
                }
            }
        }
    }
}

// ---------------------------------------------------------------------------
// MMA NATTEN flash attention. CTA = (slice, qx): 48 queries, 4 warps.
// Warps 0..2 compute m16 query tiles; per kx stage K/V hi/lo (double buffer).
// ---------------------------------------------------------------------------
#define SM_ATTN 61440   // 12KB Q + 2 stages x 24KB

__device__ __forceinline__ void attn_load_stage(uint32_t smb, size_t gb, int s)
{
    const uint32_t sb = smb + 12288 + s * 24576;
    const int tid = threadIdx.x;
    #pragma unroll
    for (int i = 0; i < 12; ++i) {
        const int id  = tid + i * 128;       // 0..1535
        const int arr = id / 384;            // 0..3
        const int u   = id - arr * 384;
        const int r   = u >> 3;              // 0..47
        const int c   = u & 7;
        const __half* src = (arr == 0) ? g_khi : (arr == 1) ? g_klo :
                            (arr == 2) ? g_vhi : g_vlo;
        cp16(sb + arr * 6144 + swz128(r, c), src + gb + (size_t)r * DHEAD + c * 8);
    }
}

__global__ __launch_bounds__(128, 2)
void natten_mma_kernel()
{
    extern __shared__ __align__(128) char sm[];
    const uint32_t smb = smem_u32(sm);
    const int tid = threadIdx.x, w = tid >> 5, lane = tid & 31;
    const int blk = blockIdx.x;
    const int slice = blk / HH;
    const int qx = blk - slice * HH;
    const size_t sbase = (size_t)slice * HW * DHEAD;

    const uint32_t SQH = smb, SQL = smb + 6144;

    // prologue: stage Q row [48,64] hi/lo
    {
        const __half* gqh = g_qhi + sbase + (size_t)qx * WW * DHEAD;
        const __half* gql = g_qlo + sbase + (size_t)qx * WW * DHEAD;
        #pragma unroll
        for (int i = 0; i < 6; ++i) {
            const int id  = tid + i * 128;   // 0..767
            const int arr = (id >= 384);
            const int u   = id - arr * 384;
            const int r   = u >> 3;
            const int c   = u & 7;
            const __half* src = arr ? gql : gqh;
            cp16((arr ? SQL : SQH) + swz128(r, c), src + (size_t)r * DHEAD + c * 8);
        }
    }
    const int kx0 = max(qx - KSZ, 0), kx1 = min(qx + KSZ, HH - 1);
    const int nkx = kx1 - kx0 + 1;
    attn_load_stage(smb, sbase + (size_t)kx0 * WW * DHEAD, 0);
    cp_commit();

    const int g = lane >> 2, ti = lane & 3;
    const int Bn = (w == 0) ? 0 : (w == 1) ? 8 : 24;   // first ky of band tiles
    const int NT = (w == 1) ? 4 : 3;                   // n8 tiles in band
    const int qyA = 16 * w + g, qyB = qyA + 8;
    uint32_t vm = 0;
    #pragma unroll
    for (int t = 0; t < 4; ++t) {
        const int ky = Bn + 8 * t + 2 * ti;
        if (abs(ky     - qyA) <= KSZ) vm |= 1u << (t * 4 + 0);
        if (abs(ky + 1 - qyA) <= KSZ) vm |= 1u << (t * 4 + 1);
        if (abs(ky     - qyB) <= KSZ) vm |= 1u << (t * 4 + 2);
        if (abs(ky + 1 - qyB) <= KSZ) vm |= 1u << (t * 4 + 3);
    }

    float m0 = -1e30f, m1 = -1e30f, l0 = 0.f, l1 = 0.f;
    float o[8][4];
    #pragma unroll
    for (int n = 0; n < 8; ++n)
        #pragma unroll
        for (int j = 0; j < 4; ++j) o[n][j] = 0.f;
    uint32_t qh[4][4], ql[4][4];

    const int a_row  = (lane & 7) + ((lane >> 3) & 1) * 8;
    const int a_chk  = lane >> 4;
    const int kb_row = lane & 7, kb_k = (lane >> 3) & 1, kb_t = lane >> 4;
    const int v_row  = (lane & 7) + ((lane >> 3) & 1) * 8;
    const int v_chk  = lane >> 4;

    for (int i = 0; i < nkx; ++i) {
        __syncthreads();     // prior-iter readers done before overwriting buffer
        if (i + 1 < nkx) {
            attn_load_stage(smb, sbase + (size_t)(kx0 + i + 1) * WW * DHEAD, (i + 1) & 1);
            cp_commit();
            cp_wait<1>();
        } else cp_wait<0>();
        __syncthreads();

        if (i == 0 && w < 3) {
            #pragma unroll
            for (int kc = 0; kc < 4; ++kc) {
                const uint32_t off = swz128(16 * w + a_row, 2 * kc + a_chk);
                ldsm_x4(qh[kc], SQH + off);
                ldsm_x4(ql[kc], SQL + off);
            }
        }
        if (w >= 3) continue;

        const uint32_t sb = smb + 12288 + (i & 1) * 24576;
        const uint32_t KH = sb, KL = sb + 6144, VH = sb + 12288, VL = sb + 18432;

        // ---- S = Q K^T (split fp16) on band tiles
        float sc4[4][4];
        #pragma unroll
        for (int t = 0; t < 4; ++t)
            #pragma unroll
            for (int j = 0; j < 4; ++j) sc4[t][j] = 0.f;
        #pragma unroll
        for (int kc = 0; kc < 4; ++kc) {
            #pragma unroll
            for (int pr = 0; pr < 2; ++pr) {
                uint32_t bh[4], bl[4];
                const uint32_t off = swz128(Bn + 8 * (2 * pr + kb_t) + kb_row, 2 * kc + kb_k);
                ldsm_x4(bh, KH + off);
                ldsm_x4(bl, KL + off);
                mma16816(sc4[2 * pr], qh[kc], bh + 0);
                mma16816(sc4[2 * pr], qh[kc], bl + 0);
                mma16816(sc4[2 * pr], ql[kc], bh + 0);
                if (2 * pr + 1 < NT) {
                    mma16816(sc4[2 * pr + 1], qh[kc], bh + 2);
                    mma16816(sc4[2 * pr + 1], qh[kc], bl + 2);
                    mma16816(sc4[2 * pr + 1], ql[kc], bh + 2);
                }
            }
        }
        // ---- mask invalid (|qy-ky| > 7)
        #pragma unroll
        for (int t = 0; t < 4; ++t)
            #pragma unroll
            for (int j = 0; j < 4; ++j)
                if (!((vm >> (t * 4 + j)) & 1)) sc4[t][j] = -1e30f;
        // ---- online softmax (exp2 domain; q pre-scaled)
        float rm0 = -1e30f, rm1 = -1e30f;
        #pragma unroll
        for (int t = 0; t < 4; ++t) {
            if (t < NT) {
                rm0 = fmaxf(rm0, fmaxf(sc4[t][0], sc4[t][1]));
                rm1 = fmaxf(rm1, fmaxf(sc4[t][2], sc4[t][3]));
            }
        }
        rm0 = fmaxf(rm0, __shfl_xor_sync(0xffffffffu, rm0, 1));
        rm0 = fmaxf(rm0, __shfl_xor_sync(0xffffffffu, rm0, 2));
        rm1 = fmaxf(rm1, __shfl_xor_sync(0xffffffffu, rm1, 1));
        rm1 = fmaxf(rm1, __shfl_xor_sync(0xffffffffu, rm1, 2));
        if (rm0 > m0) {
            const float c0 = ex2f(m0 - rm0);
            l0 *= c0;
            #pragma unroll
            for (int n = 0; n < 8; ++n) { o[n][0] *= c0; o[n][1] *= c0; }
            m0 = rm0;
        }
        if (rm1 > m1) {
            const float c1 = ex2f(m1 - rm1);
            l1 *= c1;
            #pragma unroll
            for (int n = 0; n < 8; ++n) { o[n][2] *= c1; o[n][3] *= c1; }
            m1 = rm1;
        }
        uint32_t P01[4], P23[4];
        P01[3] = P23[3] = 0u;
        #pragma unroll
        for (int t = 0; t < 4; ++t) {
            if (t < NT) {
                P01[t] = ex2h2(f16x2pack(sc4[t][1] - m0, sc4[t][0] - m0));
                P23[t] = ex2h2(f16x2pack(sc4[t][3] - m1, sc4[t][2] - m1));
                const float2 fa = __half22float2(*(__half2*)&P01[t]);
                const float2 fb = __half22float2(*(__half2*)&P23[t]);
                l0 += fa.x + fa.y;
                l1 += fb.x + fb.y;
            }
        }
        // ---- O += P V (Vhi + Vlo)
        auto pv = [&](int c, uint32_t a0, uint32_t a1, uint32_t a2, uint32_t a3) {
            const uint32_t A[4] = {a0, a1, a2, a3};
            #pragma unroll
            for (int np = 0; np < 4; ++np) {
                uint32_t vh[4], vl[4];
                const uint32_t off = swz128(16 * c + v_row, 2 * np + v_chk);
                ldsm_x4t(vh, VH + off);
                ldsm_x4t(vl, VL + off);
                mma16816(o[2 * np],     A, vh + 0);
                mma16816(o[2 * np + 1], A, vh + 2);
                mma16816(o[2 * np],     A, vl + 0);
                mma16816(o[2 * np + 1], A, vl + 2);
            }
        };
        if (w == 0) {
            pv(0, P01[0], P23[0], P01[1], P23[1]);
            pv(1, P01[2], P23[2], 0u, 0u);
        } else if (w == 1) {
            pv(0, 0u, 0u, P01[0], P23[0]);
            pv(1, P01[1], P23[1], P01[2], P23[2]);
            pv(2, P01[3], P23[3], 0u, 0u);
        } else {
            pv(1, 0u, 0u, P01[0], P23[0]);
            pv(2, P01[1], P23[1], P01[2], P23[2]);
        }
    }

    // ---- finalize: l reduce over quad, normalize, write fp16 hi/lo o
    if (w < 3) {
        l0 += __shfl_xor_sync(0xffffffffu, l0, 1);
        l0 += __shfl_xor_sync(0xffffffffu, l0, 2);
        l1 += __shfl_xor_sync(0xffffffffu, l1, 1);
        l1 += __shfl_xor_sync(0xffffffffu, l1, 2);
        const float inv0 = 1.f / l0, inv1 = 1.f / l1;
        const int nb = slice / NHEADS, head = slice - nb * NHEADS;
        const size_t rowA = ((size_t)nb * HW + (size_t)qx * WW + qyA) * DMODEL + head * DHEAD;
        const size_t rowB = ((size_t)nb * HW + (size_t)qx * WW + qyB) * DMODEL + head * DHEAD;
        #pragma unroll
        for (int np = 0; np < 8; ++np) {
            const int d = np * 8 + 2 * ti;
            {
                const float v0 = o[np][0] * inv0, v1 = o[np][1] * inv0;
                __half h0 = __float2half(v0), h1 = __float2half(v1);
                __half2 hp; hp.x = h0; hp.y = h1;
                __half2 lp; lp.x = __float2half(v0 - __half2float(h0));
                            lp.y = __float2half(v1 - __half2float(h1));
                *(__half2*)&g_ohi[rowA + d] = hp;
                *(__half2*)&g_olo[rowA + d] = lp;
            }
            {
                const float v0 = o[np][2] * inv1, v1 = o[np][3] * inv1;
                __half h0 = __float2half(v0), h1 = __float2half(v1);
                __half2 hp; hp.x = h0; hp.y = h1;
                __half2 lp; lp.x = __float2half(v0 - __half2float(h0));
                            lp.y = __float2half(v1 - __half2float(h1));
                *(__half2*)&g_ohi[rowB + d] = hp;
                *(__half2*)&g_olo[rowB + d] = lp;
            }
        }
    }
}

// ---------------------------------------------------------------------------
extern "C" void kernel_launch(void* const* d_in, const int* in_sizes, int n_in,
                              void* d_out, int out_size)
{
    const float* x     = (const float*)d_in[0];
    const float* w_qkv = (const float*)d_in[1];
    const float* w_out = (const float*)d_in[2];
    float* out = (float*)d_out;

    (void)cudaFuncSetAttribute(gemm_mma<0>, cudaFuncAttributeMaxDynamicSharedMemorySize, SMEM_GEMM);
    (void)cudaFuncSetAttribute(gemm_mma<1>, cudaFuncAttributeMaxDynamicSharedMemorySize, SMEM_GEMM);
    (void)cudaFuncSetAttribute(natten_mma_kernel, cudaFuncAttributeMaxDynamicSharedMemorySize, SM_ATTN);

    // 0) fp32 -> fp16 hi/lo splits
    {
        int n4 = M_X * DMODEL / 4;
        split_kernel<0><<<(n4 + 255) / 256, 256>>>((const float4*)x, n4);
        n4 = NQKV * DMODEL / 4;
        split_kernel<1><<<(n4 + 255) / 256, 256>>>((const float4*)w_qkv, n4);
        n4 = DMODEL * DMODEL / 4;
        split_kernel<2><<<(n4 + 255) / 256, 256>>>((const float4*)w_out, n4);
    }

    // 1) QKV projection: emits q(scaled)/k/v fp16 hi/lo
    gemm_mma<0><<<dim3(NQKV / 128, M_X / 128), 256, SMEM_GEMM>>>(nullptr);

    // 2) Neighborhood attention: 24 slices x 48 qx rows
    natten_mma_kernel<<<NBATCH * NHEADS * HH, 128, SM_ATTN>>>();

    // 3) Output projection: [4608,768] x [768,768]^T
    gemm_mma<1><<<dim3(DMODEL / 128, M_X / 128), 256, SMEM_GEMM>>>(out);
}